// round 5
// baseline (speedup 1.0000x reference)
#include <cuda_runtime.h>
#include <cuda_bf16.h>
#include <cstdint>

// out[b,f,m] = floor(log2( sum_h (x[b,f,h,0]+1)^2 * fb[m,h] )), h<257
// GEMM: M=65536, K=257 (pad 288), N=64. f32x2 FMAs.
// Occupancy-focused: 32-row CTA tile, 4x2 thread tile, W streamed per chunk.

#define ROWS_TOTAL   65536
#define KREAL        257
#define NMELS        64
#define ROW_STRIDE_X 512

#define TPB          256
#define RPC          32            // rows per CTA
#define CHUNK        32            // k floats per chunk (16 k-pairs)
#define NCHUNK       9             // 9*32 = 288 >= 257
#define KPA          36            // A row stride: conflict-free quad mapping
#define ABUF         (RPC * KPA)   // 1152 floats
#define WT           16            // k-pairs per chunk
#define WBUF         (WT * 128)    // 2048 floats: [t][64 mels][2]
#define SMEM_FLOATS  (2 * WBUF + 2 * ABUF)   // 6400 -> 25600 B

typedef unsigned long long ull;

__device__ __forceinline__ ull fma2(ull a, ull b, ull c) {
    ull d;
    asm("fma.rn.f32x2 %0, %1, %2, %3;" : "=l"(d) : "l"(a), "l"(b), "l"(c));
    return d;
}

__global__ void __launch_bounds__(TPB, 3)
lmfe_kernel(const float* __restrict__ x,
            const float* __restrict__ fb,
            float* __restrict__ out) {
    extern __shared__ float smem[];
    float* sW = smem;                 // [2][16][128]  (t-major, mel-pair packed)
    float* sA = smem + 2 * WBUF;      // [2][32][36]

    const int tid = threadIdx.x;
    const size_t rowBase = (size_t)blockIdx.x * RPC;

    // ---- staging maps ----
    // A: one float4 per thread per chunk
    const int aRowS = tid >> 3;           // 0..31
    const int aColS = tid & 7;            // 0..7  (16B units)
    const float* xRow = x + (rowBase + (size_t)aRowS) * ROW_STRIDE_X + aColS * 4;
    float* aStore = sA + aRowS * KPA + aColS * 4;
    // W: 8 scalar floats per thread per chunk
    const int wMel = tid & 63;            // 0..63
    const int wKb  = (tid >> 6) * 8;      // 0,8,16,24
    const float* fbT = fb + wMel * KREAL + wKb;
    float* wStoreBase = sW + wMel * 2;    // + tLoc*128 + parity

    // ---- stage chunk 0 ----
    float4 aSt = *reinterpret_cast<const float4*>(xRow);
    float wSt[8];
#pragma unroll
    for (int i = 0; i < 8; ++i)
        wSt[i] = (wKb + i < KREAL) ? fbT[i] : 0.0f;

    {
        float ax = aSt.x + 1.0f, ay = aSt.y + 1.0f, az = aSt.z + 1.0f, aw = aSt.w + 1.0f;
        float4 m4; m4.x = ax*ax; m4.y = ay*ay; m4.z = az*az; m4.w = aw*aw;
        *reinterpret_cast<float4*>(aStore) = m4;
#pragma unroll
        for (int i = 0; i < 8; ++i)
            wStoreBase[((wKb + i) >> 1) * 128 + (i & 1)] = wSt[i];
    }
    __syncthreads();

    // ---- compute maps ----
    const int lane = tid & 31;
    const int warp = tid >> 5;            // 0..7
    const int mg   = lane & 3;
    const int rg   = lane >> 2;           // 0..7
    const int m0   = warp * 8 + mg * 2;   // mel pair base
    // hoisted bases: all inner-loop addresses are base + immediate
    const float* wB0 = sW + m0 * 2;
    const float* wB1 = sW + WBUF + m0 * 2;
    const float* aB0 = sA + rg * KPA;
    const float* aB1 = sA + ABUF + rg * KPA;

    ull acc[4][2];
#pragma unroll
    for (int j = 0; j < 4; ++j) { acc[j][0] = 0ull; acc[j][1] = 0ull; }

#pragma unroll 1
    for (int ch = 0; ch < NCHUNK; ++ch) {
        // prefetch next chunk (gmem -> regs)
        if (ch < NCHUNK - 1) {
            aSt = *reinterpret_cast<const float4*>(xRow + (ch + 1) * CHUNK);
            const int kOff = (ch + 1) * CHUNK + wKb;
#pragma unroll
            for (int i = 0; i < 8; ++i)
                wSt[i] = (kOff + i < KREAL) ? fbT[(ch + 1) * CHUNK + i] : 0.0f;
        }

        const float* wB = (ch & 1) ? wB1 : wB0;
        const float* aB = (ch & 1) ? aB1 : aB0;

#pragma unroll
        for (int t2 = 0; t2 < 8; ++t2) {          // 2 k-pairs per step
            ulonglong2 w0 = *reinterpret_cast<const ulonglong2*>(wB + (2 * t2) * 128);
            ulonglong2 w1 = *reinterpret_cast<const ulonglong2*>(wB + (2 * t2 + 1) * 128);
            ulonglong2 a[4];
#pragma unroll
            for (int j = 0; j < 4; ++j)
                a[j] = *reinterpret_cast<const ulonglong2*>(aB + 8 * j * KPA + t2 * 4);
#pragma unroll
            for (int j = 0; j < 4; ++j) {
                acc[j][0] = fma2(a[j].x, w0.x, acc[j][0]);
                acc[j][1] = fma2(a[j].x, w0.y, acc[j][1]);
                acc[j][0] = fma2(a[j].y, w1.x, acc[j][0]);
                acc[j][1] = fma2(a[j].y, w1.y, acc[j][1]);
            }
        }

        // store next chunk (regs -> smem), then barrier
        if (ch < NCHUNK - 1) {
            float* aD = sA + ((ch + 1) & 1) * ABUF + aRowS * KPA + aColS * 4;
            float* wD = sW + ((ch + 1) & 1) * WBUF + wMel * 2;
            float ax = aSt.x + 1.0f, ay = aSt.y + 1.0f, az = aSt.z + 1.0f, aw = aSt.w + 1.0f;
            float4 m4; m4.x = ax*ax; m4.y = ay*ay; m4.z = az*az; m4.w = aw*aw;
            *reinterpret_cast<float4*>(aD) = m4;
#pragma unroll
            for (int i = 0; i < 8; ++i)
                wD[((wKb + i) >> 1) * 128 + (i & 1)] = wSt[i];
        }
        __syncthreads();
    }

    // ---- epilogue: v = lo+hi, out = floor(log2(v)) ----
#pragma unroll
    for (int j = 0; j < 4; ++j) {
        float2 o;
        {
            float2 f = *reinterpret_cast<float2*>(&acc[j][0]);
            o.x = floorf(log2f(f.x + f.y));
        }
        {
            float2 f = *reinterpret_cast<float2*>(&acc[j][1]);
            o.y = floorf(log2f(f.x + f.y));
        }
        *reinterpret_cast<float2*>(
            out + (rowBase + (size_t)(rg + 8 * j)) * NMELS + m0) = o;
    }
}

extern "C" void kernel_launch(void* const* d_in, const int* in_sizes, int n_in,
                              void* d_out, int out_size) {
    const float* x  = (const float*)d_in[0];   // (256,256,512,1) fp32
    const float* fb = (const float*)d_in[1];   // (64,257) fp32
    float* out = (float*)d_out;                // (256,256,64,1) fp32

    const int smemBytes = SMEM_FLOATS * 4;     // 25,600 B
    cudaFuncSetAttribute(lmfe_kernel,
                         cudaFuncAttributeMaxDynamicSharedMemorySize, smemBytes);

    dim3 grid(ROWS_TOTAL / RPC);               // 2048
    lmfe_kernel<<<grid, TPB, smemBytes>>>(x, fb, out);
}

// round 7
// speedup vs baseline: 1.3644x; 1.3644x over previous
#include <cuda_runtime.h>
#include <cstdint>

// out[b,f,m] = floor(log2( sum_h (x+1)^2 * fb[m,h] )), h<257
// mma.sync m16n8k8 TF32, 3-pass fp32 emulation: D = Ah*Bh + Ah*Bl + Al*Bh
// M=65536 (128/CTA), N=64, K=257 pad 288 = 9 chunks of 32 (4 k8-steps each).

#define KREAL   257
#define NMELS   64
#define XSTR    512
#define MTILE   128
#define TPB     256
#define NCHUNK  9

#define A_F2    4096              // float2 per A buffer (128 rows x 32 k)
#define B_F2    2048              // float2 per B buffer (4 t x 8 nt x 2 reg x 32 lanes)
#define SMEM_F2 (2 * (A_F2 + B_F2))   // 12288 f2 = 98304 B -> 2 CTAs/SM

__device__ float2 g_fbFrag[NCHUNK * B_F2];   // fragment-ordered filter hi/lo

__device__ __forceinline__ float tf32_hi(float v) {
    unsigned h;
    asm("cvt.rna.tf32.f32 %0, %1;" : "=r"(h) : "f"(v));
    return __uint_as_float(h);
}

__device__ __forceinline__ void mma8(float* d,
                                     unsigned a0, unsigned a1, unsigned a2, unsigned a3,
                                     unsigned b0, unsigned b1) {
    asm volatile(
        "mma.sync.aligned.m16n8k8.row.col.f32.tf32.tf32.f32 "
        "{%0,%1,%2,%3}, {%4,%5,%6,%7}, {%8,%9}, {%0,%1,%2,%3};"
        : "+f"(d[0]), "+f"(d[1]), "+f"(d[2]), "+f"(d[3])
        : "r"(a0), "r"(a1), "r"(a2), "r"(a3), "r"(b0), "r"(b1));
}

// ---- prep: fb -> fragment-ordered tf32 hi/lo, zero-padded ----
// layout: [ch][t(4)][nt(8)][reg(2)][lane(32)] ; elem (k = ch*32+t*8+reg*4+(lane&3),
//                                               n = nt*8+(lane>>2))
__global__ void prep_kernel(const float* __restrict__ fb) {
    int ch = blockIdx.x;
    for (int i = threadIdx.x; i < B_F2; i += TPB) {
        int lane = i & 31;
        int reg  = (i >> 5) & 1;
        int nt   = (i >> 6) & 7;
        int t    = (i >> 9) & 3;
        int n = nt * 8 + (lane >> 2);
        int k = ch * 32 + t * 8 + reg * 4 + (lane & 3);
        float v = (k < KREAL) ? fb[n * KREAL + k] : 0.0f;
        float h = tf32_hi(v);
        g_fbFrag[ch * B_F2 + i] = make_float2(h, v - h);
    }
}

// A fragment store: elem (row, k) -> f2 index ((slab*4+t)*4+reg)*32 + g*4 + tig
// slab=row>>4, g=row&7, hi8=(row>>3)&1; t=k>>3, kq=(k>>2)&1, tig=k&3; reg=hi8+2*kq
__device__ __forceinline__ void sts_A(float2* sAbuf, int row, int kHalf,
                                      const float4* v4) {
    const int slab = row >> 4, g = row & 7, hi8 = (row >> 3) & 1;
#pragma unroll
    for (int q = 0; q < 4; ++q) {
        int kl  = kHalf * 16 + q * 4;
        int t   = kl >> 3;
        int kq  = (kl >> 2) & 1;
        int reg = hi8 + 2 * kq;
        float2* dst = sAbuf + (((slab * 4 + t) * 4 + reg) * 32 + g * 4);
        float4 v = v4[q];
        float mx = (v.x + 1.0f) * (v.x + 1.0f);
        float my = (v.y + 1.0f) * (v.y + 1.0f);
        float mz = (v.z + 1.0f) * (v.z + 1.0f);
        float mw = (v.w + 1.0f) * (v.w + 1.0f);
        float hx = tf32_hi(mx), hy = tf32_hi(my), hz = tf32_hi(mz), hw = tf32_hi(mw);
        float4 p0, p1;
        p0.x = hx; p0.y = mx - hx; p0.z = hy; p0.w = my - hy;
        p1.x = hz; p1.y = mz - hz; p1.z = hw; p1.w = mw - hw;
        *reinterpret_cast<float4*>(dst)     = p0;
        *reinterpret_cast<float4*>(dst + 2) = p1;
    }
}

__global__ void __launch_bounds__(TPB, 2)
lmfe_kernel(const float* __restrict__ x, float* __restrict__ out) {
    extern __shared__ float2 smem[];
    float2* sA = smem;                 // [2][4096]
    float2* sB = smem + 2 * A_F2;      // [2][2048]

    const int tid  = threadIdx.x;
    const int wid  = tid >> 5;
    const int lane = tid & 31;
    const size_t rowBase = (size_t)blockIdx.x * MTILE;

    // staging maps
    const int aRow  = tid >> 1;
    const int kHalf = tid & 1;
    const float* xp = x + (rowBase + (size_t)aRow) * XSTR + kHalf * 16;
    const float4* bSrc = reinterpret_cast<const float4*>(g_fbFrag) + tid;  // +ch*1024

    // ---- stage chunk 0 ----
    {
        float4 av[4];
#pragma unroll
        for (int q = 0; q < 4; ++q)
            av[q] = *reinterpret_cast<const float4*>(xp + q * 4);
        sts_A(sA, aRow, kHalf, av);
        float4* bD = reinterpret_cast<float4*>(sB) + tid;
#pragma unroll
        for (int p = 0; p < 4; ++p)
            bD[p * TPB] = bSrc[p * TPB];
    }
    __syncthreads();

    float acc[8][4];
#pragma unroll
    for (int nt = 0; nt < 8; ++nt)
#pragma unroll
        for (int r = 0; r < 4; ++r) acc[nt][r] = 0.0f;

    float4 aPre[4], bPre[4];

#pragma unroll 1
    for (int ch = 0; ch < NCHUNK; ++ch) {
        if (ch + 1 < NCHUNK) {
#pragma unroll
            for (int q = 0; q < 4; ++q)
                aPre[q] = *reinterpret_cast<const float4*>(xp + (ch + 1) * 32 + q * 4);
#pragma unroll
            for (int p = 0; p < 4; ++p)
                bPre[p] = bSrc[(ch + 1) * (B_F2 / 2) + p * TPB];
        }

        const float2* aBuf = sA + (ch & 1) * A_F2;
        const float2* bBuf = sB + (ch & 1) * B_F2;

#pragma unroll
        for (int t = 0; t < 4; ++t) {
            const float2* aT = aBuf + ((wid * 4 + t) * 4) * 32 + lane;
            float2 a0 = aT[0], a1 = aT[32], a2 = aT[64], a3 = aT[96];
            const float2* bT = bBuf + (t * 16) * 32 + lane;
#pragma unroll
            for (int nt = 0; nt < 8; ++nt) {
                float2 b0 = bT[(nt * 2) * 32];
                float2 b1 = bT[(nt * 2 + 1) * 32];
                // pass 1: Ah*Bh ; pass 2: Ah*Bl ; pass 3: Al*Bh
                mma8(acc[nt], __float_as_uint(a0.x), __float_as_uint(a1.x),
                              __float_as_uint(a2.x), __float_as_uint(a3.x),
                              __float_as_uint(b0.x), __float_as_uint(b1.x));
                mma8(acc[nt], __float_as_uint(a0.x), __float_as_uint(a1.x),
                              __float_as_uint(a2.x), __float_as_uint(a3.x),
                              __float_as_uint(b0.y), __float_as_uint(b1.y));
                mma8(acc[nt], __float_as_uint(a0.y), __float_as_uint(a1.y),
                              __float_as_uint(a2.y), __float_as_uint(a3.y),
                              __float_as_uint(b0.x), __float_as_uint(b1.x));
            }
        }

        if (ch + 1 < NCHUNK) {
            float2* aD = sA + ((ch + 1) & 1) * A_F2;
            sts_A(aD, aRow, kHalf, aPre);
            float4* bD = reinterpret_cast<float4*>(sB + ((ch + 1) & 1) * B_F2) + tid;
#pragma unroll
            for (int p = 0; p < 4; ++p)
                bD[p * TPB] = bPre[p];
        }
        __syncthreads();
    }

    // ---- epilogue: floor(log2(v)) ----
    const int g   = lane >> 2;
    const int tig = lane & 3;
    const size_t r0 = rowBase + (size_t)(wid * 16 + g);
#pragma unroll
    for (int nt = 0; nt < 8; ++nt) {
        float2 o0, o1;
        o0.x = floorf(log2f(acc[nt][0]));
        o0.y = floorf(log2f(acc[nt][1]));
        o1.x = floorf(log2f(acc[nt][2]));
        o1.y = floorf(log2f(acc[nt][3]));
        *reinterpret_cast<float2*>(out + r0 * NMELS + nt * 8 + 2 * tig)       = o0;
        *reinterpret_cast<float2*>(out + (r0 + 8) * NMELS + nt * 8 + 2 * tig) = o1;
    }
}

extern "C" void kernel_launch(void* const* d_in, const int* in_sizes, int n_in,
                              void* d_out, int out_size) {
    const float* x  = (const float*)d_in[0];   // (256,256,512,1) fp32
    const float* fb = (const float*)d_in[1];   // (64,257) fp32
    float* out = (float*)d_out;                // (256,256,64,1) fp32

    prep_kernel<<<NCHUNK, TPB>>>(fb);

    const int smemBytes = SMEM_F2 * 8;         // 98,304 B
    cudaFuncSetAttribute(lmfe_kernel,
                         cudaFuncAttributeMaxDynamicSharedMemorySize, smemBytes);
    lmfe_kernel<<<65536 / MTILE, TPB, smemBytes>>>(x, out);   // 512 CTAs
}

// round 8
// speedup vs baseline: 1.4068x; 1.0311x over previous
#include <cuda_runtime.h>
#include <cstdint>

// out[b,f,m] = floor(log2( sum_h (x+1)^2 * fb[m,h] )), h<257
// mma.sync m16n8k8 TF32, 3-pass fp32 emulation: D = Ah*Bh + Ah*Bl + Al*Bh
// M=65536 (128/CTA), N=64, K=257 pad 288 = 9 chunks of 32 (4 k8-steps each).
// B pre-fragmented as float4 (b0hi,b0lo,b1hi,b1lo), staged via cp.async.

#define KREAL   257
#define NMELS   64
#define XSTR    512
#define MTILE   128
#define TPB     256
#define NCHUNK  9

#define A_F2    4096              // float2 per A buffer (128 rows x 32 k)
#define B_F4    1024              // float4 per B buffer: [t(4)][nt(8)][lane(32)]
#define SMEM_BYTES (2 * A_F2 * 8 + 2 * B_F4 * 16)   // 65536 + 32768 = 98304

__device__ float4 g_fbFrag[NCHUNK * B_F4];

__device__ __forceinline__ float tf32_hi(float v) {
    unsigned h;
    asm("cvt.rna.tf32.f32 %0, %1;" : "=r"(h) : "f"(v));
    return __uint_as_float(h);
}
__device__ __forceinline__ unsigned smem_u32(const void* p) {
    unsigned a;
    asm("{ .reg .u64 t; cvta.to.shared.u64 t, %1; cvt.u32.u64 %0, t; }" : "=r"(a) : "l"(p));
    return a;
}
#define CP_ASYNC16(dst, src) \
    asm volatile("cp.async.ca.shared.global [%0], [%1], 16;" :: "r"(dst), "l"(src))
#define CP_COMMIT() asm volatile("cp.async.commit_group;" ::: "memory")
#define CP_WAIT0()  asm volatile("cp.async.wait_group 0;" ::: "memory")

__device__ __forceinline__ void mma8(float* d,
                                     float a0, float a1, float a2, float a3,
                                     float b0, float b1) {
    asm volatile(
        "mma.sync.aligned.m16n8k8.row.col.f32.tf32.tf32.f32 "
        "{%0,%1,%2,%3}, {%4,%5,%6,%7}, {%8,%9}, {%0,%1,%2,%3};"
        : "+f"(d[0]), "+f"(d[1]), "+f"(d[2]), "+f"(d[3])
        : "r"(__float_as_uint(a0)), "r"(__float_as_uint(a1)),
          "r"(__float_as_uint(a2)), "r"(__float_as_uint(a3)),
          "r"(__float_as_uint(b0)), "r"(__float_as_uint(b1)));
}

// ---- prep: fb -> fragment-ordered float4 (b0hi,b0lo,b1hi,b1lo), zero-padded ----
// index [ch][t][nt][lane]: n = nt*8+(lane>>2); b0: k=ch*32+t*8+(lane&3); b1: k+4
__global__ void prep_kernel(const float* __restrict__ fb) {
    int ch = blockIdx.x;
    for (int i = threadIdx.x; i < B_F4; i += TPB) {
        int lane = i & 31;
        int nt   = (i >> 5) & 7;
        int t    = (i >> 8) & 3;
        int n  = nt * 8 + (lane >> 2);
        int k0 = ch * 32 + t * 8 + (lane & 3);
        int k1 = k0 + 4;
        float v0 = (k0 < KREAL) ? fb[n * KREAL + k0] : 0.0f;
        float v1 = (k1 < KREAL) ? fb[n * KREAL + k1] : 0.0f;
        float h0 = tf32_hi(v0), h1 = tf32_hi(v1);
        g_fbFrag[ch * B_F4 + i] = make_float4(h0, v0 - h0, h1, v1 - h1);
    }
}

// A fragment store: f2 idx (((slab*4+t)*4+reg)*32 + g*4 + tig), reg = hi8 + 2*kq
__device__ __forceinline__ void sts_A(float2* sAbuf, int row, int kHalf,
                                      const float4* v4) {
    const int slab = row >> 4, g = row & 7, hi8 = (row >> 3) & 1;
#pragma unroll
    for (int q = 0; q < 4; ++q) {
        int kl  = kHalf * 16 + q * 4;
        int t   = kl >> 3;
        int kq  = (kl >> 2) & 1;
        int reg = hi8 + 2 * kq;
        float2* dst = sAbuf + (((slab * 4 + t) * 4 + reg) * 32 + g * 4);
        float4 v = v4[q];
        float mx = (v.x + 1.0f) * (v.x + 1.0f);
        float my = (v.y + 1.0f) * (v.y + 1.0f);
        float mz = (v.z + 1.0f) * (v.z + 1.0f);
        float mw = (v.w + 1.0f) * (v.w + 1.0f);
        float hx = tf32_hi(mx), hy = tf32_hi(my), hz = tf32_hi(mz), hw = tf32_hi(mw);
        float4 p0, p1;
        p0.x = hx; p0.y = mx - hx; p0.z = hy; p0.w = my - hy;
        p1.x = hz; p1.y = mz - hz; p1.z = hw; p1.w = mw - hw;
        *reinterpret_cast<float4*>(dst)     = p0;
        *reinterpret_cast<float4*>(dst + 2) = p1;
    }
}

__global__ void __launch_bounds__(TPB, 2)
lmfe_kernel(const float* __restrict__ x, float* __restrict__ out) {
    extern __shared__ char smemRaw[];
    float2* sA = reinterpret_cast<float2*>(smemRaw);              // [2][4096] f2
    float4* sB = reinterpret_cast<float4*>(smemRaw + 2 * A_F2 * 8); // [2][1024] f4
    const unsigned sBaddr = smem_u32(sB);

    const int tid  = threadIdx.x;
    const int wid  = tid >> 5;
    const int lane = tid & 31;
    const size_t rowBase = (size_t)blockIdx.x * MTILE;

    // staging maps
    const int aRow  = tid >> 1;
    const int kHalf = tid & 1;
    const float* xp = x + (rowBase + (size_t)aRow) * XSTR + kHalf * 16;
    const float4* bSrc = g_fbFrag + tid;          // + ch*B_F4 + p*TPB

    // ---- stage chunk 0 ----
    {
#pragma unroll
        for (int p = 0; p < 4; ++p)
            CP_ASYNC16(sBaddr + (tid + p * TPB) * 16,
                       (const void*)(bSrc + p * TPB));
        CP_COMMIT();
        float4 av[4];
#pragma unroll
        for (int q = 0; q < 4; ++q)
            av[q] = *reinterpret_cast<const float4*>(xp + q * 4);
        sts_A(sA, aRow, kHalf, av);
        CP_WAIT0();
    }
    __syncthreads();

    float acc[8][4];
#pragma unroll
    for (int nt = 0; nt < 8; ++nt)
#pragma unroll
        for (int r = 0; r < 4; ++r) acc[nt][r] = 0.0f;

    float4 aPre[4];

#pragma unroll 1
    for (int ch = 0; ch < NCHUNK; ++ch) {
        if (ch + 1 < NCHUNK) {
            // next B: async copy global->smem (no regs, no scoreboard stall)
            const unsigned bDst = sBaddr + ((ch + 1) & 1) * B_F4 * 16;
            const float4* bS = bSrc + (ch + 1) * B_F4;
#pragma unroll
            for (int p = 0; p < 4; ++p)
                CP_ASYNC16(bDst + (tid + p * TPB) * 16, (const void*)(bS + p * TPB));
            CP_COMMIT();
            // next A: global prefetch into regs
#pragma unroll
            for (int q = 0; q < 4; ++q)
                aPre[q] = *reinterpret_cast<const float4*>(xp + (ch + 1) * 32 + q * 4);
        }

        const float2* aBuf = sA + (ch & 1) * A_F2;
        const float4* bBuf = sB + (ch & 1) * B_F4;

        // preload t=0 A fragment
        const float2* aT0 = aBuf + (wid * 4) * 4 * 32 + lane;
        float2 a0 = aT0[0], a1 = aT0[32], a2 = aT0[64], a3 = aT0[96];

#pragma unroll
        for (int t = 0; t < 4; ++t) {
            float2 n0, n1, n2, n3;
            if (t < 3) {
                const float2* aT = aBuf + ((wid * 4 + t + 1) * 4) * 32 + lane;
                n0 = aT[0]; n1 = aT[32]; n2 = aT[64]; n3 = aT[96];
            }
            const float4* bT = bBuf + t * 8 * 32 + lane;
#pragma unroll
            for (int nt = 0; nt < 8; ++nt) {
                float4 b = bT[nt * 32];
                mma8(acc[nt], a0.x, a1.x, a2.x, a3.x, b.x, b.z);  // Ah*Bh
                mma8(acc[nt], a0.x, a1.x, a2.x, a3.x, b.y, b.w);  // Ah*Bl
                mma8(acc[nt], a0.y, a1.y, a2.y, a3.y, b.x, b.z);  // Al*Bh
            }
            if (t < 3) { a0 = n0; a1 = n1; a2 = n2; a3 = n3; }
        }

        if (ch + 1 < NCHUNK)
            sts_A(sA + ((ch + 1) & 1) * A_F2, aRow, kHalf, aPre);
        CP_WAIT0();
        __syncthreads();
    }

    // ---- epilogue: floor(log2(v)) ----
    const int g   = lane >> 2;
    const int tig = lane & 3;
    const size_t r0 = rowBase + (size_t)(wid * 16 + g);
#pragma unroll
    for (int nt = 0; nt < 8; ++nt) {
        float2 o0, o1;
        o0.x = floorf(log2f(acc[nt][0]));
        o0.y = floorf(log2f(acc[nt][1]));
        o1.x = floorf(log2f(acc[nt][2]));
        o1.y = floorf(log2f(acc[nt][3]));
        *reinterpret_cast<float2*>(out + r0 * NMELS + nt * 8 + 2 * tig)       = o0;
        *reinterpret_cast<float2*>(out + (r0 + 8) * NMELS + nt * 8 + 2 * tig) = o1;
    }
}

extern "C" void kernel_launch(void* const* d_in, const int* in_sizes, int n_in,
                              void* d_out, int out_size) {
    const float* x  = (const float*)d_in[0];   // (256,256,512,1) fp32
    const float* fb = (const float*)d_in[1];   // (64,257) fp32
    float* out = (float*)d_out;                // (256,256,64,1) fp32

    prep_kernel<<<NCHUNK, TPB>>>(fb);

    cudaFuncSetAttribute(lmfe_kernel,
                         cudaFuncAttributeMaxDynamicSharedMemorySize, SMEM_BYTES);
    lmfe_kernel<<<65536 / MTILE, TPB, SMEM_BYTES>>>(x, out);   // 512 CTAs
}

// round 9
// speedup vs baseline: 1.6235x; 1.1541x over previous
#include <cuda_runtime.h>
#include <cstdint>

// out[b,f,m] = floor(log2( sum_h (x+1)^2 * fb[m,h] )), h<257
// mma.sync m16n8k8 TF32, 3-pass fp32 emulation: D = Ah*Bh + Ah*Bl + Al*Bh
// M=65536 (128/CTA), N=64, K=257 pad 288 = 9 chunks of 32.
// Raw x staged by cp.async (padded rows); square+hi/lo split done in registers.

#define KREAL   257
#define NMELS   64
#define XSTR    512
#define MTILE   128
#define TPB     256
#define NCHUNK  9

#define AROWB   144                         // padded row: 36 floats
#define A_BYTES (MTILE * AROWB)             // 18432 per buffer
#define B_F4    1024                        // [t(4)][nt(8)][lane(32)] float4
#define B_BYTES (B_F4 * 16)                 // 16384 per buffer
#define SMEM_BYTES (2 * A_BYTES + 2 * B_BYTES)   // 69632 -> 3 CTAs/SM

__device__ float4 g_fbFrag[NCHUNK * B_F4];

__device__ __forceinline__ float tf32_hi(float v) {
    unsigned h;
    asm("cvt.rna.tf32.f32 %0, %1;" : "=r"(h) : "f"(v));
    return __uint_as_float(h);
}
__device__ __forceinline__ unsigned smem_u32(const void* p) {
    unsigned a;
    asm("{ .reg .u64 t; cvta.to.shared.u64 t, %1; cvt.u32.u64 %0, t; }" : "=r"(a) : "l"(p));
    return a;
}
#define CP_ASYNC16(dst, src) \
    asm volatile("cp.async.ca.shared.global [%0], [%1], 16;" :: "r"(dst), "l"(src))
#define CP_COMMIT() asm volatile("cp.async.commit_group;" ::: "memory")
#define CP_WAIT0()  asm volatile("cp.async.wait_group 0;" ::: "memory")

__device__ __forceinline__ void mma8(float* d,
                                     float a0, float a1, float a2, float a3,
                                     float b0, float b1) {
    asm volatile(
        "mma.sync.aligned.m16n8k8.row.col.f32.tf32.tf32.f32 "
        "{%0,%1,%2,%3}, {%4,%5,%6,%7}, {%8,%9}, {%0,%1,%2,%3};"
        : "+f"(d[0]), "+f"(d[1]), "+f"(d[2]), "+f"(d[3])
        : "r"(__float_as_uint(a0)), "r"(__float_as_uint(a1)),
          "r"(__float_as_uint(a2)), "r"(__float_as_uint(a3)),
          "r"(__float_as_uint(b0)), "r"(__float_as_uint(b1)));
}

// ---- prep: fb -> fragment-ordered float4 (b0hi,b0lo,b1hi,b1lo), zero-padded ----
__global__ void prep_kernel(const float* __restrict__ fb) {
    int ch = blockIdx.x;
    for (int i = threadIdx.x; i < B_F4; i += TPB) {
        int lane = i & 31;
        int nt   = (i >> 5) & 7;
        int t    = (i >> 8) & 3;
        int n  = nt * 8 + (lane >> 2);
        int k0 = ch * 32 + t * 8 + (lane & 3);
        int k1 = k0 + 4;
        float v0 = (k0 < KREAL) ? fb[n * KREAL + k0] : 0.0f;
        float v1 = (k1 < KREAL) ? fb[n * KREAL + k1] : 0.0f;
        float h0 = tf32_hi(v0), h1 = tf32_hi(v1);
        g_fbFrag[ch * B_F4 + i] = make_float4(h0, v0 - h0, h1, v1 - h1);
    }
}

__global__ void __launch_bounds__(TPB, 3)
lmfe_kernel(const float* __restrict__ x, float* __restrict__ out) {
    extern __shared__ char smemRaw[];
    char*   sA = smemRaw;                        // 2 x [128][144B] raw x
    float4* sB = reinterpret_cast<float4*>(smemRaw + 2 * A_BYTES);
    const unsigned sAaddr = smem_u32(sA);
    const unsigned sBaddr = smem_u32(sB);

    const int tid  = threadIdx.x;
    const int wid  = tid >> 5;
    const int lane = tid & 31;
    const size_t rowBase = (size_t)blockIdx.x * MTILE;

    // ---- staging maps (cp.async only) ----
    const int aRow  = tid >> 1;
    const int aHalf = tid & 1;
    const float* xp = x + (rowBase + (size_t)aRow) * XSTR + aHalf * 16;  // + ch*32 + q*4
    const unsigned aDstBase = sAaddr + aRow * AROWB + aHalf * 64;        // + buf*A_BYTES + q*16
    const float4* bSrc = g_fbFrag + tid;                                 // + ch*B_F4 + p*TPB

    // ---- stage chunk 0 ----
#pragma unroll
    for (int q = 0; q < 4; ++q)
        CP_ASYNC16(aDstBase + q * 16, (const void*)(xp + q * 4));
#pragma unroll
    for (int p = 0; p < 4; ++p)
        CP_ASYNC16(sBaddr + (tid + p * TPB) * 16, (const void*)(bSrc + p * TPB));
    CP_COMMIT();
    CP_WAIT0();
    __syncthreads();

    float acc[8][4];
#pragma unroll
    for (int nt = 0; nt < 8; ++nt)
#pragma unroll
        for (int r = 0; r < 4; ++r) acc[nt][r] = 0.0f;

    // fragment A base: element (slab+g, tig) ; a1:+8 rows(1152B) ; a2:+4k(16B)
    const int g   = lane >> 2;
    const int tig = lane & 3;
    const unsigned aFragBase = sAaddr + (wid * 16 + g) * AROWB + tig * 4;
    const float* aF = reinterpret_cast<const float*>(smemRaw) +
                      ((wid * 16 + g) * AROWB + tig * 4) / 4;

#pragma unroll 1
    for (int ch = 0; ch < NCHUNK; ++ch) {
        if (ch + 1 < NCHUNK) {
            const int nb = (ch + 1) & 1;
            const unsigned aD = aDstBase + nb * A_BYTES;
            const float* aS = xp + (ch + 1) * 32;
#pragma unroll
            for (int q = 0; q < 4; ++q)
                CP_ASYNC16(aD + q * 16, (const void*)(aS + q * 4));
            const unsigned bD = sBaddr + nb * B_BYTES;
            const float4* bS = bSrc + (ch + 1) * B_F4;
#pragma unroll
            for (int p = 0; p < 4; ++p)
                CP_ASYNC16(bD + (tid + p * TPB) * 16, (const void*)(bS + p * TPB));
            CP_COMMIT();
        }

        const int b = ch & 1;
        const float*  aT = aF + (b * A_BYTES + ch * 0) / 4;  // buffer base (floats)
        const float4* bBuf = sB + b * B_F4;

        // raw A vals for t=0: offsets in floats: t*8 (+0 / +288 rows / +4)
        float r0 = aT[0],       r1 = aT[288],       r2 = aT[4],       r3 = aT[292];

#pragma unroll
        for (int t = 0; t < 4; ++t) {
            float n0, n1, n2, n3;
            if (t < 3) {
                const float* aN = aT + (t + 1) * 8;
                n0 = aN[0]; n1 = aN[288]; n2 = aN[4]; n3 = aN[292];
            }
            // square + hi/lo split in regs
            float m0 = (r0 + 1.0f) * (r0 + 1.0f);
            float m1 = (r1 + 1.0f) * (r1 + 1.0f);
            float m2 = (r2 + 1.0f) * (r2 + 1.0f);
            float m3 = (r3 + 1.0f) * (r3 + 1.0f);
            float h0 = tf32_hi(m0), h1 = tf32_hi(m1), h2 = tf32_hi(m2), h3 = tf32_hi(m3);
            float l0 = m0 - h0, l1 = m1 - h1, l2 = m2 - h2, l3 = m3 - h3;

            const float4* bT = bBuf + t * 256 + lane;
#pragma unroll
            for (int nt = 0; nt < 8; ++nt) {
                float4 bb = bT[nt * 32];
                mma8(acc[nt], h0, h1, h2, h3, bb.x, bb.z);   // Ah*Bh
                mma8(acc[nt], h0, h1, h2, h3, bb.y, bb.w);   // Ah*Bl
                mma8(acc[nt], l0, l1, l2, l3, bb.x, bb.z);   // Al*Bh
            }
            if (t < 3) { r0 = n0; r1 = n1; r2 = n2; r3 = n3; }
        }

        if (ch + 1 < NCHUNK) CP_WAIT0();
        __syncthreads();
    }

    // ---- epilogue: floor(log2(v)) = exponent field (v normal, positive) ----
    const size_t r0w = rowBase + (size_t)(wid * 16 + g);
#pragma unroll
    for (int nt = 0; nt < 8; ++nt) {
        float2 o0, o1;
        o0.x = (float)(int)(((__float_as_uint(acc[nt][0]) >> 23) & 0xFF) - 127);
        o0.y = (float)(int)(((__float_as_uint(acc[nt][1]) >> 23) & 0xFF) - 127);
        o1.x = (float)(int)(((__float_as_uint(acc[nt][2]) >> 23) & 0xFF) - 127);
        o1.y = (float)(int)(((__float_as_uint(acc[nt][3]) >> 23) & 0xFF) - 127);
        *reinterpret_cast<float2*>(out + r0w * NMELS + nt * 8 + 2 * tig)       = o0;
        *reinterpret_cast<float2*>(out + (r0w + 8) * NMELS + nt * 8 + 2 * tig) = o1;
    }
}

extern "C" void kernel_launch(void* const* d_in, const int* in_sizes, int n_in,
                              void* d_out, int out_size) {
    const float* x  = (const float*)d_in[0];   // (256,256,512,1) fp32
    const float* fb = (const float*)d_in[1];   // (64,257) fp32
    float* out = (float*)d_out;                // (256,256,64,1) fp32

    prep_kernel<<<NCHUNK, TPB>>>(fb);

    cudaFuncSetAttribute(lmfe_kernel,
                         cudaFuncAttributeMaxDynamicSharedMemorySize, SMEM_BYTES);
    lmfe_kernel<<<65536 / MTILE, TPB, SMEM_BYTES>>>(x, out);   // 512 CTAs
}

// round 10
// speedup vs baseline: 1.7910x; 1.1032x over previous
#include <cuda_runtime.h>
#include <cstdint>

// out[b,f,m] = floor(log2( sum_h (x+1)^2 * fb[m,h] )), h<257
// mma.sync m16n8k8 TF32, 3-pass fp32 emulation: D = Ah*Bh + Ah*Bl + Al*Bh
// 512-thread CTAs: 16 warps = 8 M-groups x 2 N-halves; pass-major MMA order.

#define KREAL   257
#define NMELS   64
#define XSTR    512
#define MTILE   128
#define TPB     512
#define NCHUNK  9

#define AROWB   144                         // padded row: 36 floats
#define A_BYTES (MTILE * AROWB)             // 18432 per buffer
#define B_F4    1024                        // [t(4)][nt(8)][lane(32)] float4
#define B_BYTES (B_F4 * 16)                 // 16384 per buffer
#define SMEM_BYTES (2 * A_BYTES + 2 * B_BYTES)   // 69632 -> 2 CTAs (1024 thr/SM)

__device__ float4 g_fbFrag[NCHUNK * B_F4];

__device__ __forceinline__ float tf32_hi(float v) {
    unsigned h;
    asm("cvt.rna.tf32.f32 %0, %1;" : "=r"(h) : "f"(v));
    return __uint_as_float(h);
}
__device__ __forceinline__ unsigned smem_u32(const void* p) {
    unsigned a;
    asm("{ .reg .u64 t; cvta.to.shared.u64 t, %1; cvt.u32.u64 %0, t; }" : "=r"(a) : "l"(p));
    return a;
}
#define CP_ASYNC16(dst, src) \
    asm volatile("cp.async.ca.shared.global [%0], [%1], 16;" :: "r"(dst), "l"(src))
#define CP_COMMIT() asm volatile("cp.async.commit_group;" ::: "memory")
#define CP_WAIT0()  asm volatile("cp.async.wait_group 0;" ::: "memory")

__device__ __forceinline__ void mma8(float* d,
                                     float a0, float a1, float a2, float a3,
                                     float b0, float b1) {
    asm volatile(
        "mma.sync.aligned.m16n8k8.row.col.f32.tf32.tf32.f32 "
        "{%0,%1,%2,%3}, {%4,%5,%6,%7}, {%8,%9}, {%0,%1,%2,%3};"
        : "+f"(d[0]), "+f"(d[1]), "+f"(d[2]), "+f"(d[3])
        : "r"(__float_as_uint(a0)), "r"(__float_as_uint(a1)),
          "r"(__float_as_uint(a2)), "r"(__float_as_uint(a3)),
          "r"(__float_as_uint(b0)), "r"(__float_as_uint(b1)));
}

// ---- prep: fb -> fragment-ordered float4 (b0hi,b0lo,b1hi,b1lo), zero-padded ----
__global__ void prep_kernel(const float* __restrict__ fb) {
    int ch = blockIdx.x;
    for (int i = threadIdx.x; i < B_F4; i += blockDim.x) {
        int lane = i & 31;
        int nt   = (i >> 5) & 7;
        int t    = (i >> 8) & 3;
        int n  = nt * 8 + (lane >> 2);
        int k0 = ch * 32 + t * 8 + (lane & 3);
        int k1 = k0 + 4;
        float v0 = (k0 < KREAL) ? fb[n * KREAL + k0] : 0.0f;
        float v1 = (k1 < KREAL) ? fb[n * KREAL + k1] : 0.0f;
        float h0 = tf32_hi(v0), h1 = tf32_hi(v1);
        g_fbFrag[ch * B_F4 + i] = make_float4(h0, v0 - h0, h1, v1 - h1);
    }
}

__global__ void __launch_bounds__(TPB, 2)
lmfe_kernel(const float* __restrict__ x, float* __restrict__ out) {
    extern __shared__ char smemRaw[];
    char*   sA = smemRaw;                        // 2 x [128][144B] raw x
    float4* sB = reinterpret_cast<float4*>(smemRaw + 2 * A_BYTES);
    const unsigned sAaddr = smem_u32(sA);
    const unsigned sBaddr = smem_u32(sB);

    const int tid  = threadIdx.x;
    const int wid  = tid >> 5;
    const int lane = tid & 31;
    const size_t rowBase = (size_t)blockIdx.x * MTILE;

    // ---- staging maps: A: thread -> (row = tid>>2, 8 floats at (tid&3)*8) ----
    const int aRow = tid >> 2;
    const int aQ   = tid & 3;
    const float* xp = x + (rowBase + (size_t)aRow) * XSTR + aQ * 8;  // + ch*32
    const unsigned aDstBase = sAaddr + aRow * AROWB + aQ * 32;       // + buf*A_BYTES
    const float4* bSrc = g_fbFrag + tid;                             // + ch*B_F4 + p*TPB

    // ---- stage chunk 0 ----
    CP_ASYNC16(aDstBase,      (const void*)xp);
    CP_ASYNC16(aDstBase + 16, (const void*)(xp + 4));
    CP_ASYNC16(sBaddr + tid * 16,         (const void*)bSrc);
    CP_ASYNC16(sBaddr + (tid + TPB) * 16, (const void*)(bSrc + TPB));
    CP_COMMIT();
    CP_WAIT0();
    __syncthreads();

    float acc[4][4];
#pragma unroll
    for (int nt = 0; nt < 4; ++nt)
#pragma unroll
        for (int r = 0; r < 4; ++r) acc[nt][r] = 0.0f;

    // warp tile: M group = wid&7 (16 rows), N half = wid>>3 (4 nt)
    const int mGrp  = wid & 7;
    const int nHalf = wid >> 3;
    const int g   = lane >> 2;
    const int tig = lane & 3;
    // A fragment float offset within buffer: (mGrp*16+g)*36 + tig ; +288 rows, +4 k
    const float* aF = reinterpret_cast<const float*>(smemRaw) + (mGrp * 16 + g) * 36 + tig;

#pragma unroll 1
    for (int ch = 0; ch < NCHUNK; ++ch) {
        if (ch + 1 < NCHUNK) {
            const int nb = (ch + 1) & 1;
            const float* aS = xp + (ch + 1) * 32;
            CP_ASYNC16(aDstBase + nb * A_BYTES,      (const void*)aS);
            CP_ASYNC16(aDstBase + nb * A_BYTES + 16, (const void*)(aS + 4));
            const unsigned bD = sBaddr + nb * B_BYTES;
            const float4* bS = bSrc + (ch + 1) * B_F4;
            CP_ASYNC16(bD + tid * 16,         (const void*)bS);
            CP_ASYNC16(bD + (tid + TPB) * 16, (const void*)(bS + TPB));
            CP_COMMIT();
        }

        const int b = ch & 1;
        const float*  aT   = aF + b * (A_BYTES / 4);
        const float4* bBuf = sB + b * B_F4 + nHalf * 128 + lane;   // + t*256 + nt*32

#pragma unroll
        for (int t = 0; t < 4; ++t) {
            // B fragments for this t (4 nt), loaded up-front
            float4 b0 = bBuf[t * 256];
            float4 b1 = bBuf[t * 256 + 32];
            float4 b2 = bBuf[t * 256 + 64];
            float4 b3 = bBuf[t * 256 + 96];
            // A raw -> square -> hi/lo
            const float* aP = aT + t * 8;
            float r0 = aP[0], r1 = aP[288], r2 = aP[4], r3 = aP[292];
            float m0 = (r0 + 1.0f) * (r0 + 1.0f);
            float m1 = (r1 + 1.0f) * (r1 + 1.0f);
            float m2 = (r2 + 1.0f) * (r2 + 1.0f);
            float m3 = (r3 + 1.0f) * (r3 + 1.0f);
            float h0 = tf32_hi(m0), h1 = tf32_hi(m1), h2 = tf32_hi(m2), h3 = tf32_hi(m3);
            float l0 = m0 - h0, l1 = m1 - h1, l2 = m2 - h2, l3 = m3 - h3;

            // pass-major: accumulator reuse distance = 4 MMAs
            mma8(acc[0], h0, h1, h2, h3, b0.x, b0.z);
            mma8(acc[1], h0, h1, h2, h3, b1.x, b1.z);
            mma8(acc[2], h0, h1, h2, h3, b2.x, b2.z);
            mma8(acc[3], h0, h1, h2, h3, b3.x, b3.z);
            mma8(acc[0], h0, h1, h2, h3, b0.y, b0.w);
            mma8(acc[1], h0, h1, h2, h3, b1.y, b1.w);
            mma8(acc[2], h0, h1, h2, h3, b2.y, b2.w);
            mma8(acc[3], h0, h1, h2, h3, b3.y, b3.w);
            mma8(acc[0], l0, l1, l2, l3, b0.x, b0.z);
            mma8(acc[1], l0, l1, l2, l3, b1.x, b1.z);
            mma8(acc[2], l0, l1, l2, l3, b2.x, b2.z);
            mma8(acc[3], l0, l1, l2, l3, b3.x, b3.z);
        }

        if (ch + 1 < NCHUNK) CP_WAIT0();
        __syncthreads();
    }

    // ---- epilogue: floor(log2(v)) = exponent field (v normal, positive) ----
    const size_t r0w  = rowBase + (size_t)(mGrp * 16 + g);
    const int    col0 = nHalf * 32 + 2 * tig;
#pragma unroll
    for (int nt = 0; nt < 4; ++nt) {
        float2 o0, o1;
        o0.x = (float)(int)(((__float_as_uint(acc[nt][0]) >> 23) & 0xFF) - 127);
        o0.y = (float)(int)(((__float_as_uint(acc[nt][1]) >> 23) & 0xFF) - 127);
        o1.x = (float)(int)(((__float_as_uint(acc[nt][2]) >> 23) & 0xFF) - 127);
        o1.y = (float)(int)(((__float_as_uint(acc[nt][3]) >> 23) & 0xFF) - 127);
        *reinterpret_cast<float2*>(out + r0w * NMELS + col0 + nt * 8)       = o0;
        *reinterpret_cast<float2*>(out + (r0w + 8) * NMELS + col0 + nt * 8) = o1;
    }
}

extern "C" void kernel_launch(void* const* d_in, const int* in_sizes, int n_in,
                              void* d_out, int out_size) {
    const float* x  = (const float*)d_in[0];   // (256,256,512,1) fp32
    const float* fb = (const float*)d_in[1];   // (64,257) fp32
    float* out = (float*)d_out;                // (256,256,64,1) fp32

    prep_kernel<<<NCHUNK, 256>>>(fb);

    cudaFuncSetAttribute(lmfe_kernel,
                         cudaFuncAttributeMaxDynamicSharedMemorySize, SMEM_BYTES);
    lmfe_kernel<<<65536 / MTILE, TPB, SMEM_BYTES>>>(x, out);   // 512 CTAs
}

// round 11
// speedup vs baseline: 1.9214x; 1.0728x over previous
#include <cuda_runtime.h>
#include <cstdint>

// out[b,f,m] = floor(log2( sum_h (x+1)^2 * fb[m,h] )), h<257
// mma.sync m16n8k8 TF32 3-pass emulation over k=0..255 (8 chunks of 32),
// k=256 handled as exact fp32 rank-1 update in the epilogue.
// Persistent CTAs + atomic tile ticket (512 tiles of 128 rows).

#define KREAL   257
#define NMELS   64
#define XSTR    512
#define MTILE   128
#define TPB     512
#define NCHUNK  8
#define NTILES  512
#define GRID    304

#define AROWB   144                         // padded row: 36 floats
#define A_BYTES (MTILE * AROWB)             // 18432 per buffer
#define B_F4    1024                        // [t(4)][nt(8)][lane(32)] float4
#define B_BYTES (B_F4 * 16)                 // 16384 per buffer
#define EDGE_OFF (2 * A_BYTES + 2 * B_BYTES)       // 69632
#define SMEM_BYTES (EDGE_OFF + (MTILE + NMELS) * 4) // 70400

__device__ float4 g_fbFrag[NCHUNK * B_F4];
__device__ unsigned g_ticket;

__device__ __forceinline__ float tf32_hi(float v) {
    unsigned h;
    asm("cvt.rna.tf32.f32 %0, %1;" : "=r"(h) : "f"(v));
    return __uint_as_float(h);
}
__device__ __forceinline__ unsigned smem_u32(const void* p) {
    unsigned a;
    asm("{ .reg .u64 t; cvta.to.shared.u64 t, %1; cvt.u32.u64 %0, t; }" : "=r"(a) : "l"(p));
    return a;
}
#define CP_ASYNC16(dst, src) \
    asm volatile("cp.async.ca.shared.global [%0], [%1], 16;" :: "r"(dst), "l"(src))
#define CP_COMMIT() asm volatile("cp.async.commit_group;" ::: "memory")
#define CP_WAIT0()  asm volatile("cp.async.wait_group 0;" ::: "memory")

__device__ __forceinline__ void mma8(float* d,
                                     float a0, float a1, float a2, float a3,
                                     float b0, float b1) {
    asm volatile(
        "mma.sync.aligned.m16n8k8.row.col.f32.tf32.tf32.f32 "
        "{%0,%1,%2,%3}, {%4,%5,%6,%7}, {%8,%9}, {%0,%1,%2,%3};"
        : "+f"(d[0]), "+f"(d[1]), "+f"(d[2]), "+f"(d[3])
        : "r"(__float_as_uint(a0)), "r"(__float_as_uint(a1)),
          "r"(__float_as_uint(a2)), "r"(__float_as_uint(a3)),
          "r"(__float_as_uint(b0)), "r"(__float_as_uint(b1)));
}

__global__ void reset_kernel() { g_ticket = GRID; }

// ---- prep: fb -> fragment-ordered float4 (b0hi,b0lo,b1hi,b1lo), k<256 ----
__global__ void prep_kernel(const float* __restrict__ fb) {
    int ch = blockIdx.x;
    for (int i = threadIdx.x; i < B_F4; i += blockDim.x) {
        int lane = i & 31;
        int nt   = (i >> 5) & 7;
        int t    = (i >> 8) & 3;
        int n  = nt * 8 + (lane >> 2);
        int k0 = ch * 32 + t * 8 + (lane & 3);
        float v0 = fb[n * KREAL + k0];
        float v1 = fb[n * KREAL + k0 + 4];
        float h0 = tf32_hi(v0), h1 = tf32_hi(v1);
        g_fbFrag[ch * B_F4 + i] = make_float4(h0, v0 - h0, h1, v1 - h1);
    }
}

__global__ void __launch_bounds__(TPB, 2)
lmfe_kernel(const float* __restrict__ x, const float* __restrict__ fb,
            float* __restrict__ out) {
    extern __shared__ char smemRaw[];
    float4* sB    = reinterpret_cast<float4*>(smemRaw + 2 * A_BYTES);
    float*  sMag  = reinterpret_cast<float*>(smemRaw + EDGE_OFF);       // [128]
    float*  sFbc  = sMag + MTILE;                                       // [64]
    __shared__ unsigned sTile;
    const unsigned sAaddr = smem_u32(smemRaw);
    const unsigned sBaddr = smem_u32(sB);

    const int tid  = threadIdx.x;
    const int wid  = tid >> 5;
    const int lane = tid & 31;

    // fb[:,256] once (never overwritten)
    if (tid < NMELS) sFbc[tid] = fb[tid * KREAL + 256];

    // staging maps
    const int aRow = tid >> 2;
    const int aQ   = tid & 3;
    const unsigned aDstBase = sAaddr + aRow * AROWB + aQ * 32;
    const float4* bSrcBase = g_fbFrag + tid;

    // warp tile map
    const int mGrp  = wid & 7;
    const int nHalf = wid >> 3;
    const int g   = lane >> 2;
    const int tig = lane & 3;
    const float* aF = reinterpret_cast<const float*>(smemRaw) + (mGrp * 16 + g) * 36 + tig;
    const int row0L = mGrp * 16 + g;
    const int col0  = nHalf * 32 + 2 * tig;

    unsigned tile = blockIdx.x;

#pragma unroll 1
    while (tile < NTILES) {
        const size_t rowBase = (size_t)tile * MTILE;
        const float* xp = x + (rowBase + (size_t)aRow) * XSTR + aQ * 8;

        // ---- stage chunk 0 + mag256 column ----
        CP_ASYNC16(aDstBase,      (const void*)xp);
        CP_ASYNC16(aDstBase + 16, (const void*)(xp + 4));
        CP_ASYNC16(sBaddr + tid * 16,         (const void*)bSrcBase);
        CP_ASYNC16(sBaddr + (tid + TPB) * 16, (const void*)(bSrcBase + TPB));
        CP_COMMIT();
        if (tid < MTILE) {
            float v = x[(rowBase + (size_t)tid) * XSTR + 256] + 1.0f;
            sMag[tid] = v * v;
        }
        CP_WAIT0();
        __syncthreads();

        float acc[4][4];
#pragma unroll
        for (int nt = 0; nt < 4; ++nt)
#pragma unroll
            for (int r = 0; r < 4; ++r) acc[nt][r] = 0.0f;

#pragma unroll 1
        for (int ch = 0; ch < NCHUNK; ++ch) {
            if (ch + 1 < NCHUNK) {
                const int nb = (ch + 1) & 1;
                const float* aS = xp + (ch + 1) * 32;
                CP_ASYNC16(aDstBase + nb * A_BYTES,      (const void*)aS);
                CP_ASYNC16(aDstBase + nb * A_BYTES + 16, (const void*)(aS + 4));
                const unsigned bD = sBaddr + nb * B_BYTES;
                const float4* bS = bSrcBase + (ch + 1) * B_F4;
                CP_ASYNC16(bD + tid * 16,         (const void*)bS);
                CP_ASYNC16(bD + (tid + TPB) * 16, (const void*)(bS + TPB));
                CP_COMMIT();
            }

            const int b = ch & 1;
            const float*  aT   = aF + b * (A_BYTES / 4);
            const float4* bBuf = sB + b * B_F4 + nHalf * 128 + lane;

#pragma unroll
            for (int t = 0; t < 4; ++t) {
                float4 b0 = bBuf[t * 256];
                float4 b1 = bBuf[t * 256 + 32];
                float4 b2 = bBuf[t * 256 + 64];
                float4 b3 = bBuf[t * 256 + 96];
                const float* aP = aT + t * 8;
                float r0 = aP[0], r1 = aP[288], r2 = aP[4], r3 = aP[292];
                float m0 = (r0 + 1.0f) * (r0 + 1.0f);
                float m1 = (r1 + 1.0f) * (r1 + 1.0f);
                float m2 = (r2 + 1.0f) * (r2 + 1.0f);
                float m3 = (r3 + 1.0f) * (r3 + 1.0f);
                float h0 = tf32_hi(m0), h1 = tf32_hi(m1);
                float h2 = tf32_hi(m2), h3 = tf32_hi(m3);
                float l0 = m0 - h0, l1 = m1 - h1, l2 = m2 - h2, l3 = m3 - h3;

                mma8(acc[0], h0, h1, h2, h3, b0.x, b0.z);
                mma8(acc[1], h0, h1, h2, h3, b1.x, b1.z);
                mma8(acc[2], h0, h1, h2, h3, b2.x, b2.z);
                mma8(acc[3], h0, h1, h2, h3, b3.x, b3.z);
                mma8(acc[0], h0, h1, h2, h3, b0.y, b0.w);
                mma8(acc[1], h0, h1, h2, h3, b1.y, b1.w);
                mma8(acc[2], h0, h1, h2, h3, b2.y, b2.w);
                mma8(acc[3], h0, h1, h2, h3, b3.y, b3.w);
                mma8(acc[0], l0, l1, l2, l3, b0.x, b0.z);
                mma8(acc[1], l0, l1, l2, l3, b1.x, b1.z);
                mma8(acc[2], l0, l1, l2, l3, b2.x, b2.z);
                mma8(acc[3], l0, l1, l2, l3, b3.x, b3.z);
            }

            if (ch + 1 < NCHUNK) CP_WAIT0();
            __syncthreads();
        }

        // ---- epilogue: add exact k=256 term, then exponent extract ----
        const float a0m = sMag[row0L];
        const float a1m = sMag[row0L + 8];
        const size_t r0w = rowBase + (size_t)row0L;
#pragma unroll
        for (int nt = 0; nt < 4; ++nt) {
            float2 fc = *reinterpret_cast<const float2*>(sFbc + col0 + nt * 8);
            float v00 = fmaf(a0m, fc.x, acc[nt][0]);
            float v01 = fmaf(a0m, fc.y, acc[nt][1]);
            float v10 = fmaf(a1m, fc.x, acc[nt][2]);
            float v11 = fmaf(a1m, fc.y, acc[nt][3]);
            float2 o0, o1;
            o0.x = (float)(int)(((__float_as_uint(v00) >> 23) & 0xFF) - 127);
            o0.y = (float)(int)(((__float_as_uint(v01) >> 23) & 0xFF) - 127);
            o1.x = (float)(int)(((__float_as_uint(v10) >> 23) & 0xFF) - 127);
            o1.y = (float)(int)(((__float_as_uint(v11) >> 23) & 0xFF) - 127);
            *reinterpret_cast<float2*>(out + r0w * NMELS + col0 + nt * 8)       = o0;
            *reinterpret_cast<float2*>(out + (r0w + 8) * NMELS + col0 + nt * 8) = o1;
        }

        // ---- next tile via ticket ----
        __syncthreads();
        if (tid == 0) sTile = atomicAdd(&g_ticket, 1u);
        __syncthreads();
        tile = sTile;
    }
}

extern "C" void kernel_launch(void* const* d_in, const int* in_sizes, int n_in,
                              void* d_out, int out_size) {
    const float* x  = (const float*)d_in[0];   // (256,256,512,1) fp32
    const float* fb = (const float*)d_in[1];   // (64,257) fp32
    float* out = (float*)d_out;                // (256,256,64,1) fp32

    reset_kernel<<<1, 1>>>();
    prep_kernel<<<NCHUNK, 256>>>(fb);

    cudaFuncSetAttribute(lmfe_kernel,
                         cudaFuncAttributeMaxDynamicSharedMemorySize, SMEM_BYTES);
    lmfe_kernel<<<GRID, TPB, SMEM_BYTES>>>(x, fb, out);
}